// round 14
// baseline (speedup 1.0000x reference)
#include <cuda_runtime.h>
#include <cuda_fp16.h>
#include <cstdint>

#define BB 2
#define TT 2048
#define CC 1024
#define HH 16
#define DD 64
#define BHTD (BB*HH*TT*DD)   // 4,194,304

// ---------------------------------------------------------------------------
// Scratch (__device__ globals; allocation-free rule)
// ---------------------------------------------------------------------------
__device__ __align__(16) __half g_x_hi[4096ll * 1024];
__device__ __align__(16) __half g_x_lo[4096ll * 1024];
__device__ __align__(16) __half g_wq[3072ll * 1024];        // w_attn^T [N,K] single fp16
__device__ __align__(16) __half g_wp[1024ll * 1024];        // w_proj^T [N,K] single fp16
__device__ __align__(16) __half g_att[4096ll * 1024];       // attn out [M,K] single fp16
// QKV outputs, [B*H, T, D]: q split hi/lo (pre-scaled by 0.125*log2e), k/v single
__device__ __align__(16) __half g_q_hi[BHTD];
__device__ __align__(16) __half g_q_lo[BHTD];
__device__ __align__(16) __half g_k[BHTD];
__device__ __align__(16) __half g_v[BHTD];

// ---------------------------------------------------------------------------
// Helpers
// ---------------------------------------------------------------------------
__device__ __forceinline__ uint32_t smem_u32(const void* p) {
    uint32_t a;
    asm("{ .reg .u64 t; cvta.to.shared.u64 t, %1; cvt.u32.u64 %0, t; }" : "=r"(a) : "l"(p));
    return a;
}
__device__ __forceinline__ void cp_async16(uint32_t dst, const void* src) {
    asm volatile("cp.async.cg.shared.global [%0], [%1], 16;" :: "r"(dst), "l"(src));
}
#define CP_COMMIT() asm volatile("cp.async.commit_group;" ::: "memory")
__device__ __forceinline__ uint32_t sw64(uint32_t off)  { return off ^ ((off >> 3) & 0x30); }
__device__ __forceinline__ uint32_t sw128(uint32_t off) { return off ^ ((off >> 3) & 0x70); }

__device__ __forceinline__ void ldsm4(uint32_t* r, uint32_t addr) {
    asm volatile("ldmatrix.sync.aligned.m8n8.x4.shared.b16 {%0,%1,%2,%3}, [%4];"
        : "=r"(r[0]), "=r"(r[1]), "=r"(r[2]), "=r"(r[3]) : "r"(addr));
}
__device__ __forceinline__ void ldsm4t(uint32_t* r, uint32_t addr) {
    asm volatile("ldmatrix.sync.aligned.m8n8.x4.trans.shared.b16 {%0,%1,%2,%3}, [%4];"
        : "=r"(r[0]), "=r"(r[1]), "=r"(r[2]), "=r"(r[3]) : "r"(addr));
}
// fp16 MMA with fp32 accumulate
__device__ __forceinline__ void mma16816(float* d, const uint32_t* a, const uint32_t* b) {
    asm volatile("mma.sync.aligned.m16n8k16.row.col.f32.f16.f16.f32 "
        "{%0,%1,%2,%3}, {%4,%5,%6,%7}, {%8,%9}, {%0,%1,%2,%3};"
        : "+f"(d[0]), "+f"(d[1]), "+f"(d[2]), "+f"(d[3])
        : "r"(a[0]), "r"(a[1]), "r"(a[2]), "r"(a[3]), "r"(b[0]), "r"(b[1]));
}
__device__ __forceinline__ void split2h(float x, float y, uint32_t& hi, uint32_t& lo) {
    __half hx = __float2half_rn(x), hy = __float2half_rn(y);
    __half lx = __float2half_rn(x - __half2float(hx));
    __half ly = __float2half_rn(y - __half2float(hy));
    __half2 h2 = __halves2half2(hx, hy);
    __half2 l2 = __halves2half2(lx, ly);
    hi = *reinterpret_cast<uint32_t*>(&h2);
    lo = *reinterpret_cast<uint32_t*>(&l2);
}
__device__ __forceinline__ uint32_t pack2h(float x, float y) {
    __half2 h = __floats2half2_rn(x, y);
    return *reinterpret_cast<uint32_t*>(&h);
}

// ---------------------------------------------------------------------------
// Prepass kernels
// ---------------------------------------------------------------------------
__global__ void split_kernel(const float* __restrict__ X,
                             __half* __restrict__ hi, __half* __restrict__ lo)
{
    int i = blockIdx.x * blockDim.x + threadIdx.x;
    float4 v = ((const float4*)X)[i];
    uint32_t h0, l0, h1, l1;
    split2h(v.x, v.y, h0, l0);
    split2h(v.z, v.w, h1, l1);
    *(uint32_t*)(hi + (size_t)i * 4)     = h0;
    *(uint32_t*)(hi + (size_t)i * 4 + 2) = h1;
    *(uint32_t*)(lo + (size_t)i * 4)     = l0;
    *(uint32_t*)(lo + (size_t)i * 4 + 2) = l1;
}

// Fused transpose of both weight matrices: W [K,N] fp32 -> T [N,K] fp16.
__global__ void tboth_kernel(const float* __restrict__ Wq,
                             const float* __restrict__ Wp,
                             __half* __restrict__ Tq,
                             __half* __restrict__ Tp)
{
    __shared__ float ts[32][33];
    const float* W;
    __half* T;
    int Ncols, bx = blockIdx.x;
    if (bx < 96) { W = Wq; T = Tq; Ncols = 3072; }
    else         { W = Wp; T = Tp; Ncols = 1024; bx -= 96; }
    int n0 = bx * 32, k0 = blockIdx.y * 32;
    int tx = threadIdx.x, ty = threadIdx.y;
    ts[ty][tx] = W[(size_t)(k0 + ty) * Ncols + n0 + tx];
    __syncthreads();
    T[(size_t)(n0 + ty) * 1024 + k0 + tx] = __float2half_rn(ts[tx][ty]);
}

// ---------------------------------------------------------------------------
// fp16 GEMM via mma.sync, TERMS in {1,2} (R12 structure, unchanged).
// ---------------------------------------------------------------------------
#define ARR   8192                  // 128 rows x 64B
#define NSTG 3
#define NK 32

template<int TERMS>
__device__ __forceinline__ void load_stage(
    int tid, int kt, uint32_t sbase,
    const __half* Ahi, const __half* Alo, const __half* Bh,
    int m0, int n0)
{
    constexpr int STAGE = (TERMS + 1) * ARR;
    const uint32_t st = sbase + (uint32_t)((kt % NSTG) * STAGE);
    const int k0 = kt * 32;
    #pragma unroll
    for (int i = 0; i < 4; i++) {
        int idx = tid + i * 128;                 // 0..511 16B-chunks
        int r = idx >> 2, c = idx & 3;
        uint32_t d = sw64((uint32_t)idx * 16);
        size_t goA = (size_t)(m0 + r) * 1024 + k0 + c * 8;
        size_t goB = (size_t)(n0 + r) * 1024 + k0 + c * 8;
        cp_async16(st + d, Ahi + goA);
        if (TERMS == 2) cp_async16(st + ARR + d, Alo + goA);
        cp_async16(st + TERMS * ARR + d, Bh + goB);
    }
    CP_COMMIT();
}

template<bool QKV_EP, int TERMS>
__global__ void __launch_bounds__(128, 2) gemm_mma(
    const __half* __restrict__ Ahi, const __half* __restrict__ Alo,
    const __half* __restrict__ Bh2,
    const float* __restrict__ bias, float* __restrict__ Cout, int N)
{
    constexpr int STAGE = (TERMS + 1) * ARR;
    extern __shared__ __align__(128) char smem[];
    const uint32_t sb = smem_u32(smem);
    const int tid  = threadIdx.x;
    const int wid  = tid >> 5;
    const int lane = tid & 31;
    const int m0 = blockIdx.y * 128;
    const int n0 = blockIdx.x * 128;
    const int warpM = (wid >> 1) * 64;
    const int warpN = (wid & 1) * 64;

    float acc[4][8][4];
    #pragma unroll
    for (int i = 0; i < 4; i++)
        #pragma unroll
        for (int j = 0; j < 8; j++)
            #pragma unroll
            for (int e = 0; e < 4; e++) acc[i][j][e] = 0.f;

    const uint32_t aL = (uint32_t)((warpM + (lane & 15)) * 64 + (lane >> 4) * 16);
    const int brow = (lane & 7) + ((lane >> 4) << 3);
    const uint32_t bL = (uint32_t)((warpN + brow) * 64 + ((lane >> 3) & 1) * 16);

    load_stage<TERMS>(tid, 0, sb, Ahi, Alo, Bh2, m0, n0);
    load_stage<TERMS>(tid, 1, sb, Ahi, Alo, Bh2, m0, n0);

    for (int kt = 0; kt < NK; kt++) {
        if (kt + 1 < NK) asm volatile("cp.async.wait_group 1;" ::: "memory");
        else             asm volatile("cp.async.wait_group 0;" ::: "memory");
        __syncthreads();
        if (kt + 2 < NK)
            load_stage<TERMS>(tid, kt + 2, sb, Ahi, Alo, Bh2, m0, n0);

        const uint32_t st = sb + (uint32_t)((kt % NSTG) * STAGE);
        #pragma unroll
        for (int ks = 0; ks < 2; ks++) {
            uint32_t ah[4][4], al[4][4], bh[8][2];
            #pragma unroll
            for (int mt = 0; mt < 4; mt++) {
                uint32_t d = sw64(aL + (uint32_t)(mt * 1024 + ks * 32));
                ldsm4(ah[mt], st + d);
                if (TERMS == 2) ldsm4(al[mt], st + ARR + d);
            }
            #pragma unroll
            for (int np = 0; np < 4; np++) {
                uint32_t d = sw64(bL + (uint32_t)(np * 1024 + ks * 32));
                uint32_t r[4];
                ldsm4(r, st + TERMS * ARR + d);
                bh[np*2][0] = r[0]; bh[np*2][1] = r[1];
                bh[np*2+1][0] = r[2]; bh[np*2+1][1] = r[3];
            }
            #pragma unroll
            for (int mt = 0; mt < 4; mt++)
                #pragma unroll
                for (int nt = 0; nt < 8; nt++)
                    mma16816(acc[mt][nt], ah[mt], bh[nt]);
            if (TERMS == 2) {
                #pragma unroll
                for (int mt = 0; mt < 4; mt++)
                    #pragma unroll
                    for (int nt = 0; nt < 8; nt++)
                        mma16816(acc[mt][nt], al[mt], bh[nt]);
            }
        }
    }

    const int gid = lane >> 2;
    const int tig = lane & 3;
    const float QSCALE = 0.18033688011112042f;   // 0.125 * log2(e)
    #pragma unroll
    for (int mt = 0; mt < 4; mt++) {
        #pragma unroll
        for (int nt = 0; nt < 8; nt++) {
            int n = n0 + warpN + nt * 8 + tig * 2;
            float bx = bias[n], by = bias[n + 1];
            #pragma unroll
            for (int half = 0; half < 2; half++) {
                int m = m0 + warpM + mt * 16 + gid + half * 8;
                float vx = acc[mt][nt][half * 2 + 0] + bx;
                float vy = acc[mt][nt][half * 2 + 1] + by;
                if (QKV_EP) {
                    int which = n >> 10;
                    int hh = (n >> 6) & 15;
                    int dd = n & 63;
                    int bb = m >> 11;
                    int tt = m & 2047;
                    size_t off = (((size_t)bb * HH + hh) * TT + tt) * DD + dd;
                    if (which == 0) {
                        uint32_t hi, lo;
                        split2h(vx * QSCALE, vy * QSCALE, hi, lo);
                        *(uint32_t*)(g_q_hi + off) = hi;
                        *(uint32_t*)(g_q_lo + off) = lo;
                    } else {
                        __half* p = (which == 1) ? g_k : g_v;
                        *(uint32_t*)(p + off) = pack2h(vx, vy);
                    }
                } else {
                    float2 v; v.x = vx; v.y = vy;
                    *(float2*)(Cout + (size_t)m * N + n) = v;
                }
            }
        }
    }
}

#define GEMM_SMEM2 (NSTG * 3 * ARR)   // TERMS=2: 73728
#define GEMM_SMEM1 (NSTG * 2 * ARR)   // TERMS=1: 49152

// ---------------------------------------------------------------------------
// fp16 flash attention: Q split 2-term, K/V/P single. SW128, 128B rows.
// 3-buffer K/V ring (prefetch distance 2). Smem 64KB -> 2 CTAs/SM.
// exp2-domain softmax with warp-voted rescale skip. fp16 attn-out.
// ---------------------------------------------------------------------------
#define AT_TILE 8192                              // 64 rows x 128B
#define KV_BUF (2 * AT_TILE)                      // K,V = 16384
#define ATT_SMEM (2 * AT_TILE + 3 * KV_BUF)       // 65536

__device__ __forceinline__ void attn_load_kv(
    int tid, uint32_t dst, const __half* Kp, const __half* Vp)
{
    for (int i = tid; i < 512; i += 128) {
        uint32_t d = sw128((uint32_t)i * 16);
        size_t go = (size_t)i * 8;
        cp_async16(dst + d,           Kp + go);
        cp_async16(dst + AT_TILE + d, Vp + go);
    }
    CP_COMMIT();
}

__global__ void __launch_bounds__(128, 2) attn_mma()
{
    extern __shared__ __align__(128) char smem[];
    const uint32_t sb = smem_u32(smem);
    const int tid  = threadIdx.x;
    const int wid  = tid >> 5;
    const int lane = tid & 31;
    const int bh = blockIdx.y;
    const int q0 = (int)(gridDim.x - 1 - blockIdx.x) * 64;   // big tiles first
    const int warpM = wid * 16;
    const size_t bhoff = (size_t)bh * TT * DD;

    const uint32_t kv0 = sb + 2 * AT_TILE;
    const int njt = q0 / 64 + 1;

    // --- group A: Q tile (hi+lo) + K/V tile 0, one commit ---
    {
        const __half* Qh = g_q_hi + bhoff + (size_t)q0 * DD;
        const __half* Ql = g_q_lo + bhoff + (size_t)q0 * DD;
        for (int i = tid; i < 512; i += 128) {
            uint32_t d = sw128((uint32_t)i * 16);
            size_t go = (size_t)i * 8;
            cp_async16(sb + d,           Qh + go);
            cp_async16(sb + AT_TILE + d, Ql + go);
        }
        const __half* Kp = g_k + bhoff;
        const __half* Vp = g_v + bhoff;
        for (int i = tid; i < 512; i += 128) {
            uint32_t d = sw128((uint32_t)i * 16);
            size_t go = (size_t)i * 8;
            cp_async16(kv0 + d,           Kp + go);
            cp_async16(kv0 + AT_TILE + d, Vp + go);
        }
        CP_COMMIT();
    }
    // --- group B: K/V tile 1 ---
    if (njt > 1)
        attn_load_kv(tid, kv0 + KV_BUF, g_k + bhoff + 64 * DD, g_v + bhoff + 64 * DD);

    if (njt > 1) asm volatile("cp.async.wait_group 1;" ::: "memory");
    else         asm volatile("cp.async.wait_group 0;" ::: "memory");
    __syncthreads();

    uint32_t qh[4][4], ql[4][4];
    const uint32_t aL = (uint32_t)((warpM + (lane & 15)) * 128 + (lane >> 4) * 16);
    #pragma unroll
    for (int ks = 0; ks < 4; ks++) {
        uint32_t d = sw128(aL + (uint32_t)(ks * 32));
        ldsm4(qh[ks], sb + d);
        ldsm4(ql[ks], sb + AT_TILE + d);
    }

    float o[8][4];
    #pragma unroll
    for (int i = 0; i < 8; i++)
        #pragma unroll
        for (int e = 0; e < 4; e++) o[i][e] = 0.f;
    float m0 = -1e30f, m1 = -1e30f, l0 = 0.f, l1 = 0.f;

    const int brow = (lane & 7) + ((lane >> 4) << 3);
    const uint32_t bL = (uint32_t)(brow * 128 + ((lane >> 3) & 1) * 16);
    const int vrow = (lane & 7) + ((lane >> 3) & 1) * 8;
    const uint32_t vL = (uint32_t)(vrow * 128 + (lane >> 4) * 16);

    // ring index helper: buffer j%3
    for (int jt = 0; jt < njt; jt++) {
        // prefetch jt+2 into buffer (jt+2)%3 (freed by end-sync of jt-1)
        if (jt + 2 < njt) {
            size_t jo = (size_t)(jt + 2) * 64 * DD;
            attn_load_kv(tid, kv0 + (uint32_t)(((jt + 2) % 3) * KV_BUF),
                         g_k + bhoff + jo, g_v + bhoff + jo);
        }
        int rem = njt - 1 - jt;     // groups committed after tile jt
        if (rem >= 2)      asm volatile("cp.async.wait_group 2;" ::: "memory");
        else if (rem == 1) asm volatile("cp.async.wait_group 1;" ::: "memory");
        else               asm volatile("cp.async.wait_group 0;" ::: "memory");
        __syncthreads();

        const uint32_t kb = kv0 + (uint32_t)((jt % 3) * KV_BUF);

        float s[8][4];
        #pragma unroll
        for (int i = 0; i < 8; i++)
            #pragma unroll
            for (int e = 0; e < 4; e++) s[i][e] = 0.f;

        // S = (Qh+Ql) Kh^T  (2 terms), scores in log2 units
        #pragma unroll
        for (int ks = 0; ks < 4; ks++) {
            #pragma unroll
            for (int np = 0; np < 4; np++) {
                uint32_t rh[4];
                uint32_t d = sw128(bL + (uint32_t)(np * 16 * 128 + ks * 32));
                ldsm4(rh, kb + d);
                uint32_t bh0[2] = {rh[0], rh[1]}, bh1[2] = {rh[2], rh[3]};
                mma16816(s[np*2],   qh[ks], bh0);
                mma16816(s[np*2+1], qh[ks], bh1);
                mma16816(s[np*2],   ql[ks], bh0);
                mma16816(s[np*2+1], ql[ks], bh1);
            }
        }

        if (jt == njt - 1) {
            int r0 = warpM + (lane >> 2);
            #pragma unroll
            for (int nt = 0; nt < 8; nt++) {
                int c0 = nt * 8 + (lane & 3) * 2;
                #pragma unroll
                for (int e = 0; e < 4; e++) {
                    int row = r0 + (e >> 1) * 8;
                    int col = c0 + (e & 1);
                    if (col > row) s[nt][e] = -1e30f;
                }
            }
        }

        float tm0 = -1e30f, tm1 = -1e30f;
        #pragma unroll
        for (int nt = 0; nt < 8; nt++) {
            tm0 = fmaxf(tm0, fmaxf(s[nt][0], s[nt][1]));
            tm1 = fmaxf(tm1, fmaxf(s[nt][2], s[nt][3]));
        }
        tm0 = fmaxf(tm0, __shfl_xor_sync(0xffffffff, tm0, 1));
        tm0 = fmaxf(tm0, __shfl_xor_sync(0xffffffff, tm0, 2));
        tm1 = fmaxf(tm1, __shfl_xor_sync(0xffffffff, tm1, 1));
        tm1 = fmaxf(tm1, __shfl_xor_sync(0xffffffff, tm1, 2));

        float nm0 = fmaxf(m0, tm0), nm1 = fmaxf(m1, tm1);
        float c0s = exp2f(m0 - nm0), c1s = exp2f(m1 - nm1);
        m0 = nm0; m1 = nm1;

        float ls0 = 0.f, ls1 = 0.f;
        #pragma unroll
        for (int nt = 0; nt < 8; nt++) {
            s[nt][0] = exp2f(s[nt][0] - nm0); ls0 += s[nt][0];
            s[nt][1] = exp2f(s[nt][1] - nm0); ls0 += s[nt][1];
            s[nt][2] = exp2f(s[nt][2] - nm1); ls1 += s[nt][2];
            s[nt][3] = exp2f(s[nt][3] - nm1); ls1 += s[nt][3];
        }
        ls0 += __shfl_xor_sync(0xffffffff, ls0, 1);
        ls0 += __shfl_xor_sync(0xffffffff, ls0, 2);
        ls1 += __shfl_xor_sync(0xffffffff, ls1, 1);
        ls1 += __shfl_xor_sync(0xffffffff, ls1, 2);

        // warp-voted rescale skip: exp2f(0) == 1.0f exactly
        if (__all_sync(0xffffffff, (c0s == 1.f) & (c1s == 1.f))) {
            l0 += ls0;
            l1 += ls1;
        } else {
            l0 = l0 * c0s + ls0;
            l1 = l1 * c1s + ls1;
            #pragma unroll
            for (int dt = 0; dt < 8; dt++) {
                o[dt][0] *= c0s; o[dt][1] *= c0s;
                o[dt][2] *= c1s; o[dt][3] *= c1s;
            }
        }

        // P single fp16 A-fragments
        uint32_t ph[4][4];
        #pragma unroll
        for (int ksv = 0; ksv < 4; ksv++) {
            ph[ksv][0] = pack2h(s[2*ksv][0],   s[2*ksv][1]);
            ph[ksv][1] = pack2h(s[2*ksv][2],   s[2*ksv][3]);
            ph[ksv][2] = pack2h(s[2*ksv+1][0], s[2*ksv+1][1]);
            ph[ksv][3] = pack2h(s[2*ksv+1][2], s[2*ksv+1][3]);
        }

        // O += P Vh  (1 term)
        const uint32_t vb = kb + AT_TILE;
        #pragma unroll
        for (int ksv = 0; ksv < 4; ksv++) {
            #pragma unroll
            for (int dg = 0; dg < 4; dg++) {
                uint32_t rh[4];
                uint32_t d = sw128(vL + (uint32_t)(ksv * 16 * 128 + dg * 32));
                ldsm4t(rh, vb + d);
                uint32_t vh0[2] = {rh[0], rh[1]}, vh1[2] = {rh[2], rh[3]};
                mma16816(o[dg*2],   ph[ksv], vh0);
                mma16816(o[dg*2+1], ph[ksv], vh1);
            }
        }
        __syncthreads();
    }

    // epilogue: single fp16 attn-out
    float inv0 = 1.f / l0, inv1 = 1.f / l1;
    int qi = q0 + warpM + (lane >> 2);
    size_t ro0 = ((size_t)(bh >> 4) * TT + qi) * CC + (size_t)(bh & 15) * DD;
    size_t ro1 = ro0 + (size_t)8 * CC;
    #pragma unroll
    for (int dt = 0; dt < 8; dt++) {
        int col = dt * 8 + (lane & 3) * 2;
        *(uint32_t*)(g_att + ro0 + col) = pack2h(o[dt][0] * inv0, o[dt][1] * inv0);
        *(uint32_t*)(g_att + ro1 + col) = pack2h(o[dt][2] * inv1, o[dt][3] * inv1);
    }
}

// ---------------------------------------------------------------------------
extern "C" void kernel_launch(void* const* d_in, const int* in_sizes, int n_in,
                              void* d_out, int out_size)
{
    const float* x      = (const float*)d_in[0];
    const float* w_attn = (const float*)d_in[1];
    const float* b_attn = (const float*)d_in[2];
    const float* w_proj = (const float*)d_in[3];
    const float* b_proj = (const float*)d_in[4];
    float* out = (float*)d_out;

    __half *xh, *xl, *wq, *wp, *att;
    cudaGetSymbolAddress((void**)&xh,  g_x_hi);
    cudaGetSymbolAddress((void**)&xl,  g_x_lo);
    cudaGetSymbolAddress((void**)&wq,  g_wq);
    cudaGetSymbolAddress((void**)&wp,  g_wp);
    cudaGetSymbolAddress((void**)&att, g_att);

    cudaFuncSetAttribute((const void*)gemm_mma<true, 2>,
                         cudaFuncAttributeMaxDynamicSharedMemorySize, GEMM_SMEM2);
    cudaFuncSetAttribute((const void*)gemm_mma<false, 1>,
                         cudaFuncAttributeMaxDynamicSharedMemorySize, GEMM_SMEM1);
    cudaFuncSetAttribute(attn_mma, cudaFuncAttributeMaxDynamicSharedMemorySize, ATT_SMEM);

    split_kernel<<<4096, 256>>>(x, xh, xl);
    tboth_kernel<<<dim3(128, 32), dim3(32, 32)>>>(w_attn, w_proj, wq, wp);

    gemm_mma<true, 2><<<dim3(24, 32), 128, GEMM_SMEM2>>>(xh, xl, wq, b_attn, nullptr, 3072);
    attn_mma<<<dim3(TT / 64, BB * HH), 128, ATT_SMEM>>>();
    gemm_mma<false, 1><<<dim3(8, 32), 128, GEMM_SMEM1>>>(att, nullptr, wp, b_proj, out, 1024);
}

// round 15
// speedup vs baseline: 1.0149x; 1.0149x over previous
#include <cuda_runtime.h>
#include <cuda_fp16.h>
#include <cstdint>

#define BB 2
#define TT 2048
#define CC 1024
#define HH 16
#define DD 64
#define BHTD (BB*HH*TT*DD)   // 4,194,304

// ---------------------------------------------------------------------------
// Scratch (__device__ globals; allocation-free rule)
// ---------------------------------------------------------------------------
__device__ __align__(16) __half g_x_hi[4096ll * 1024];
__device__ __align__(16) __half g_x_lo[4096ll * 1024];
__device__ __align__(16) __half g_wq[3072ll * 1024];        // w_attn^T [N,K] single fp16
__device__ __align__(16) __half g_wp[1024ll * 1024];        // w_proj^T [N,K] single fp16
__device__ __align__(16) __half g_att[4096ll * 1024];       // attn out [M,K] single fp16
// QKV outputs, [B*H, T, D]: q split hi/lo (pre-scaled by 0.125*log2e), k/v single
__device__ __align__(16) __half g_q_hi[BHTD];
__device__ __align__(16) __half g_q_lo[BHTD];
__device__ __align__(16) __half g_k[BHTD];
__device__ __align__(16) __half g_v[BHTD];

// ---------------------------------------------------------------------------
// Helpers
// ---------------------------------------------------------------------------
__device__ __forceinline__ uint32_t smem_u32(const void* p) {
    uint32_t a;
    asm("{ .reg .u64 t; cvta.to.shared.u64 t, %1; cvt.u32.u64 %0, t; }" : "=r"(a) : "l"(p));
    return a;
}
__device__ __forceinline__ void cp_async16(uint32_t dst, const void* src) {
    asm volatile("cp.async.cg.shared.global [%0], [%1], 16;" :: "r"(dst), "l"(src));
}
#define CP_COMMIT() asm volatile("cp.async.commit_group;" ::: "memory")
__device__ __forceinline__ uint32_t sw64(uint32_t off)  { return off ^ ((off >> 3) & 0x30); }
__device__ __forceinline__ uint32_t sw128(uint32_t off) { return off ^ ((off >> 3) & 0x70); }

__device__ __forceinline__ void ldsm4(uint32_t* r, uint32_t addr) {
    asm volatile("ldmatrix.sync.aligned.m8n8.x4.shared.b16 {%0,%1,%2,%3}, [%4];"
        : "=r"(r[0]), "=r"(r[1]), "=r"(r[2]), "=r"(r[3]) : "r"(addr));
}
__device__ __forceinline__ void ldsm4t(uint32_t* r, uint32_t addr) {
    asm volatile("ldmatrix.sync.aligned.m8n8.x4.trans.shared.b16 {%0,%1,%2,%3}, [%4];"
        : "=r"(r[0]), "=r"(r[1]), "=r"(r[2]), "=r"(r[3]) : "r"(addr));
}
// fp16 MMA with fp32 accumulate
__device__ __forceinline__ void mma16816(float* d, const uint32_t* a, const uint32_t* b) {
    asm volatile("mma.sync.aligned.m16n8k16.row.col.f32.f16.f16.f32 "
        "{%0,%1,%2,%3}, {%4,%5,%6,%7}, {%8,%9}, {%0,%1,%2,%3};"
        : "+f"(d[0]), "+f"(d[1]), "+f"(d[2]), "+f"(d[3])
        : "r"(a[0]), "r"(a[1]), "r"(a[2]), "r"(a[3]), "r"(b[0]), "r"(b[1]));
}
__device__ __forceinline__ void split2h(float x, float y, uint32_t& hi, uint32_t& lo) {
    __half hx = __float2half_rn(x), hy = __float2half_rn(y);
    __half lx = __float2half_rn(x - __half2float(hx));
    __half ly = __float2half_rn(y - __half2float(hy));
    __half2 h2 = __halves2half2(hx, hy);
    __half2 l2 = __halves2half2(lx, ly);
    hi = *reinterpret_cast<uint32_t*>(&h2);
    lo = *reinterpret_cast<uint32_t*>(&l2);
}
__device__ __forceinline__ uint32_t pack2h(float x, float y) {
    __half2 h = __floats2half2_rn(x, y);
    return *reinterpret_cast<uint32_t*>(&h);
}

// ---------------------------------------------------------------------------
// Prepass kernels
// ---------------------------------------------------------------------------
__global__ void split_kernel(const float* __restrict__ X,
                             __half* __restrict__ hi, __half* __restrict__ lo)
{
    int i = blockIdx.x * blockDim.x + threadIdx.x;
    float4 v = ((const float4*)X)[i];
    uint32_t h0, l0, h1, l1;
    split2h(v.x, v.y, h0, l0);
    split2h(v.z, v.w, h1, l1);
    *(uint32_t*)(hi + (size_t)i * 4)     = h0;
    *(uint32_t*)(hi + (size_t)i * 4 + 2) = h1;
    *(uint32_t*)(lo + (size_t)i * 4)     = l0;
    *(uint32_t*)(lo + (size_t)i * 4 + 2) = l1;
}

// Fused transpose of both weight matrices: W [K,N] fp32 -> T [N,K] fp16.
__global__ void tboth_kernel(const float* __restrict__ Wq,
                             const float* __restrict__ Wp,
                             __half* __restrict__ Tq,
                             __half* __restrict__ Tp)
{
    __shared__ float ts[32][33];
    const float* W;
    __half* T;
    int Ncols, bx = blockIdx.x;
    if (bx < 96) { W = Wq; T = Tq; Ncols = 3072; }
    else         { W = Wp; T = Tp; Ncols = 1024; bx -= 96; }
    int n0 = bx * 32, k0 = blockIdx.y * 32;
    int tx = threadIdx.x, ty = threadIdx.y;
    ts[ty][tx] = W[(size_t)(k0 + ty) * Ncols + n0 + tx];
    __syncthreads();
    T[(size_t)(n0 + ty) * 1024 + k0 + tx] = __float2half_rn(ts[tx][ty]);
}

// ---------------------------------------------------------------------------
// fp16 GEMM via mma.sync, TERMS in {1,2} (R12 structure, unchanged).
// ---------------------------------------------------------------------------
#define ARR   8192                  // 128 rows x 64B
#define NSTG 3
#define NK 32

template<int TERMS>
__device__ __forceinline__ void load_stage(
    int tid, int kt, uint32_t sbase,
    const __half* Ahi, const __half* Alo, const __half* Bh,
    int m0, int n0)
{
    constexpr int STAGE = (TERMS + 1) * ARR;
    const uint32_t st = sbase + (uint32_t)((kt % NSTG) * STAGE);
    const int k0 = kt * 32;
    #pragma unroll
    for (int i = 0; i < 4; i++) {
        int idx = tid + i * 128;                 // 0..511 16B-chunks
        int r = idx >> 2, c = idx & 3;
        uint32_t d = sw64((uint32_t)idx * 16);
        size_t goA = (size_t)(m0 + r) * 1024 + k0 + c * 8;
        size_t goB = (size_t)(n0 + r) * 1024 + k0 + c * 8;
        cp_async16(st + d, Ahi + goA);
        if (TERMS == 2) cp_async16(st + ARR + d, Alo + goA);
        cp_async16(st + TERMS * ARR + d, Bh + goB);
    }
    CP_COMMIT();
}

template<bool QKV_EP, int TERMS>
__global__ void __launch_bounds__(128, 2) gemm_mma(
    const __half* __restrict__ Ahi, const __half* __restrict__ Alo,
    const __half* __restrict__ Bh2,
    const float* __restrict__ bias, float* __restrict__ Cout, int N)
{
    constexpr int STAGE = (TERMS + 1) * ARR;
    extern __shared__ __align__(128) char smem[];
    const uint32_t sb = smem_u32(smem);
    const int tid  = threadIdx.x;
    const int wid  = tid >> 5;
    const int lane = tid & 31;
    const int m0 = blockIdx.y * 128;
    const int n0 = blockIdx.x * 128;
    const int warpM = (wid >> 1) * 64;
    const int warpN = (wid & 1) * 64;

    float acc[4][8][4];
    #pragma unroll
    for (int i = 0; i < 4; i++)
        #pragma unroll
        for (int j = 0; j < 8; j++)
            #pragma unroll
            for (int e = 0; e < 4; e++) acc[i][j][e] = 0.f;

    const uint32_t aL = (uint32_t)((warpM + (lane & 15)) * 64 + (lane >> 4) * 16);
    const int brow = (lane & 7) + ((lane >> 4) << 3);
    const uint32_t bL = (uint32_t)((warpN + brow) * 64 + ((lane >> 3) & 1) * 16);

    load_stage<TERMS>(tid, 0, sb, Ahi, Alo, Bh2, m0, n0);
    load_stage<TERMS>(tid, 1, sb, Ahi, Alo, Bh2, m0, n0);

    for (int kt = 0; kt < NK; kt++) {
        if (kt + 1 < NK) asm volatile("cp.async.wait_group 1;" ::: "memory");
        else             asm volatile("cp.async.wait_group 0;" ::: "memory");
        __syncthreads();
        if (kt + 2 < NK)
            load_stage<TERMS>(tid, kt + 2, sb, Ahi, Alo, Bh2, m0, n0);

        const uint32_t st = sb + (uint32_t)((kt % NSTG) * STAGE);
        #pragma unroll
        for (int ks = 0; ks < 2; ks++) {
            uint32_t ah[4][4], al[4][4], bh[8][2];
            #pragma unroll
            for (int mt = 0; mt < 4; mt++) {
                uint32_t d = sw64(aL + (uint32_t)(mt * 1024 + ks * 32));
                ldsm4(ah[mt], st + d);
                if (TERMS == 2) ldsm4(al[mt], st + ARR + d);
            }
            #pragma unroll
            for (int np = 0; np < 4; np++) {
                uint32_t d = sw64(bL + (uint32_t)(np * 1024 + ks * 32));
                uint32_t r[4];
                ldsm4(r, st + TERMS * ARR + d);
                bh[np*2][0] = r[0]; bh[np*2][1] = r[1];
                bh[np*2+1][0] = r[2]; bh[np*2+1][1] = r[3];
            }
            #pragma unroll
            for (int mt = 0; mt < 4; mt++)
                #pragma unroll
                for (int nt = 0; nt < 8; nt++)
                    mma16816(acc[mt][nt], ah[mt], bh[nt]);
            if (TERMS == 2) {
                #pragma unroll
                for (int mt = 0; mt < 4; mt++)
                    #pragma unroll
                    for (int nt = 0; nt < 8; nt++)
                        mma16816(acc[mt][nt], al[mt], bh[nt]);
            }
        }
    }

    const int gid = lane >> 2;
    const int tig = lane & 3;
    const float QSCALE = 0.18033688011112042f;   // 0.125 * log2(e)
    #pragma unroll
    for (int mt = 0; mt < 4; mt++) {
        #pragma unroll
        for (int nt = 0; nt < 8; nt++) {
            int n = n0 + warpN + nt * 8 + tig * 2;
            float bx = bias[n], by = bias[n + 1];
            #pragma unroll
            for (int half = 0; half < 2; half++) {
                int m = m0 + warpM + mt * 16 + gid + half * 8;
                float vx = acc[mt][nt][half * 2 + 0] + bx;
                float vy = acc[mt][nt][half * 2 + 1] + by;
                if (QKV_EP) {
                    int which = n >> 10;
                    int hh = (n >> 6) & 15;
                    int dd = n & 63;
                    int bb = m >> 11;
                    int tt = m & 2047;
                    size_t off = (((size_t)bb * HH + hh) * TT + tt) * DD + dd;
                    if (which == 0) {
                        uint32_t hi, lo;
                        split2h(vx * QSCALE, vy * QSCALE, hi, lo);
                        *(uint32_t*)(g_q_hi + off) = hi;
                        *(uint32_t*)(g_q_lo + off) = lo;
                    } else {
                        __half* p = (which == 1) ? g_k : g_v;
                        *(uint32_t*)(p + off) = pack2h(vx, vy);
                    }
                } else {
                    float2 v; v.x = vx; v.y = vy;
                    *(float2*)(Cout + (size_t)m * N + n) = v;
                }
            }
        }
    }
}

#define GEMM_SMEM2 (NSTG * 3 * ARR)   // TERMS=2: 73728
#define GEMM_SMEM1 (NSTG * 2 * ARR)   // TERMS=1: 49152

// ---------------------------------------------------------------------------
// fp16 flash attention (R12 config): Q split 2-term, K/V/P single. SW128,
// 128B rows, double-buffered. Smem 48KB -> 2 CTAs/SM. exp2-domain softmax.
// Row-sum of P computed by MMA against a ones-B fragment (no scalar adds or
// shuffles). Warp-voted rescale skip. fp16 attn-out.
// ---------------------------------------------------------------------------
#define AT_TILE 8192                              // 64 rows x 128B
#define KV_BUF (2 * AT_TILE)                      // K,V = 16384
#define ATT_SMEM (2 * AT_TILE + 2 * KV_BUF)       // 49152

__global__ void __launch_bounds__(128, 2) attn_mma()
{
    extern __shared__ __align__(128) char smem[];
    const uint32_t sb = smem_u32(smem);
    const int tid  = threadIdx.x;
    const int wid  = tid >> 5;
    const int lane = tid & 31;
    const int bh = blockIdx.y;
    const int q0 = (int)(gridDim.x - 1 - blockIdx.x) * 64;   // big tiles first
    const int warpM = wid * 16;
    const size_t bhoff = (size_t)bh * TT * DD;

    const uint32_t kv0 = sb + 2 * AT_TILE;

    // --- load Q tile (hi+lo), SW128 ---
    {
        const __half* Qh = g_q_hi + bhoff + (size_t)q0 * DD;
        const __half* Ql = g_q_lo + bhoff + (size_t)q0 * DD;
        for (int i = tid; i < 512; i += 128) {
            uint32_t d = sw128((uint32_t)i * 16);
            size_t go = (size_t)i * 8;
            cp_async16(sb + d,           Qh + go);
            cp_async16(sb + AT_TILE + d, Ql + go);
        }
        CP_COMMIT();
    }

    const int njt = q0 / 64 + 1;

    // --- load K/V tile 0 ---
    {
        const __half* Kp = g_k + bhoff;
        const __half* Vp = g_v + bhoff;
        for (int i = tid; i < 512; i += 128) {
            uint32_t d = sw128((uint32_t)i * 16);
            size_t go = (size_t)i * 8;
            cp_async16(kv0 + d,           Kp + go);
            cp_async16(kv0 + AT_TILE + d, Vp + go);
        }
        CP_COMMIT();
    }

    asm volatile("cp.async.wait_group 1;" ::: "memory");
    __syncthreads();
    uint32_t qh[4][4], ql[4][4];
    const uint32_t aL = (uint32_t)((warpM + (lane & 15)) * 128 + (lane >> 4) * 16);
    #pragma unroll
    for (int ks = 0; ks < 4; ks++) {
        uint32_t d = sw128(aL + (uint32_t)(ks * 32));
        ldsm4(qh[ks], sb + d);
        ldsm4(ql[ks], sb + AT_TILE + d);
    }

    float o[8][4];
    #pragma unroll
    for (int i = 0; i < 8; i++)
        #pragma unroll
        for (int e = 0; e < 4; e++) o[i][e] = 0.f;
    float m0 = -1e30f, m1 = -1e30f, l0 = 0.f, l1 = 0.f;

    const uint32_t ones2[2] = {0x3C003C00u, 0x3C003C00u};   // fp16 1.0 x4

    const int brow = (lane & 7) + ((lane >> 4) << 3);
    const uint32_t bL = (uint32_t)(brow * 128 + ((lane >> 3) & 1) * 16);
    const int vrow = (lane & 7) + ((lane >> 3) & 1) * 8;
    const uint32_t vL = (uint32_t)(vrow * 128 + (lane >> 4) * 16);

    for (int jt = 0; jt < njt; jt++) {
        if (jt + 1 < njt) {
            uint32_t nb = kv0 + (uint32_t)(((jt + 1) & 1) * KV_BUF);
            size_t jo = (size_t)(jt + 1) * 64 * DD;
            const __half* Kp = g_k + bhoff + jo;
            const __half* Vp = g_v + bhoff + jo;
            for (int i = tid; i < 512; i += 128) {
                uint32_t d = sw128((uint32_t)i * 16);
                size_t go = (size_t)i * 8;
                cp_async16(nb + d,           Kp + go);
                cp_async16(nb + AT_TILE + d, Vp + go);
            }
            CP_COMMIT();
            asm volatile("cp.async.wait_group 1;" ::: "memory");
        } else {
            asm volatile("cp.async.wait_group 0;" ::: "memory");
        }
        __syncthreads();

        const uint32_t kb = kv0 + (uint32_t)((jt & 1) * KV_BUF);

        float s[8][4];
        #pragma unroll
        for (int i = 0; i < 8; i++)
            #pragma unroll
            for (int e = 0; e < 4; e++) s[i][e] = 0.f;

        // S = (Qh+Ql) Kh^T  (2 terms), scores in log2 units
        #pragma unroll
        for (int ks = 0; ks < 4; ks++) {
            #pragma unroll
            for (int np = 0; np < 4; np++) {
                uint32_t rh[4];
                uint32_t d = sw128(bL + (uint32_t)(np * 16 * 128 + ks * 32));
                ldsm4(rh, kb + d);
                uint32_t bh0[2] = {rh[0], rh[1]}, bh1[2] = {rh[2], rh[3]};
                mma16816(s[np*2],   qh[ks], bh0);
                mma16816(s[np*2+1], qh[ks], bh1);
                mma16816(s[np*2],   ql[ks], bh0);
                mma16816(s[np*2+1], ql[ks], bh1);
            }
        }

        if (jt == njt - 1) {
            int r0 = warpM + (lane >> 2);
            #pragma unroll
            for (int nt = 0; nt < 8; nt++) {
                int c0 = nt * 8 + (lane & 3) * 2;
                #pragma unroll
                for (int e = 0; e < 4; e++) {
                    int row = r0 + (e >> 1) * 8;
                    int col = c0 + (e & 1);
                    if (col > row) s[nt][e] = -1e30f;
                }
            }
        }

        float tm0 = -1e30f, tm1 = -1e30f;
        #pragma unroll
        for (int nt = 0; nt < 8; nt++) {
            tm0 = fmaxf(tm0, fmaxf(s[nt][0], s[nt][1]));
            tm1 = fmaxf(tm1, fmaxf(s[nt][2], s[nt][3]));
        }
        tm0 = fmaxf(tm0, __shfl_xor_sync(0xffffffff, tm0, 1));
        tm0 = fmaxf(tm0, __shfl_xor_sync(0xffffffff, tm0, 2));
        tm1 = fmaxf(tm1, __shfl_xor_sync(0xffffffff, tm1, 1));
        tm1 = fmaxf(tm1, __shfl_xor_sync(0xffffffff, tm1, 2));

        float nm0 = fmaxf(m0, tm0), nm1 = fmaxf(m1, tm1);
        float c0s = exp2f(m0 - nm0), c1s = exp2f(m1 - nm1);
        m0 = nm0; m1 = nm1;

        // exp (fp32) and pack P into fp16 A-fragments
        uint32_t ph[4][4];
        #pragma unroll
        for (int nt = 0; nt < 8; nt++) {
            s[nt][0] = exp2f(s[nt][0] - nm0);
            s[nt][1] = exp2f(s[nt][1] - nm0);
            s[nt][2] = exp2f(s[nt][2] - nm1);
            s[nt][3] = exp2f(s[nt][3] - nm1);
        }
        #pragma unroll
        for (int ksv = 0; ksv < 4; ksv++) {
            ph[ksv][0] = pack2h(s[2*ksv][0],   s[2*ksv][1]);
            ph[ksv][1] = pack2h(s[2*ksv][2],   s[2*ksv][3]);
            ph[ksv][2] = pack2h(s[2*ksv+1][0], s[2*ksv+1][1]);
            ph[ksv][3] = pack2h(s[2*ksv+1][2], s[2*ksv+1][3]);
        }

        // Row sums of P via MMA against ones-B: every lane gets its row's sum
        float lsum[4] = {0.f, 0.f, 0.f, 0.f};
        #pragma unroll
        for (int ksv = 0; ksv < 4; ksv++)
            mma16816(lsum, ph[ksv], ones2);

        // warp-voted rescale skip (exp2f(0) == 1.0f exactly)
        if (__all_sync(0xffffffff, (c0s == 1.f) & (c1s == 1.f))) {
            l0 += lsum[0];
            l1 += lsum[2];
        } else {
            l0 = l0 * c0s + lsum[0];
            l1 = l1 * c1s + lsum[2];
            #pragma unroll
            for (int dt = 0; dt < 8; dt++) {
                o[dt][0] *= c0s; o[dt][1] *= c0s;
                o[dt][2] *= c1s; o[dt][3] *= c1s;
            }
        }

        // O += P Vh  (1 term)
        const uint32_t vb = kb + AT_TILE;
        #pragma unroll
        for (int ksv = 0; ksv < 4; ksv++) {
            #pragma unroll
            for (int dg = 0; dg < 4; dg++) {
                uint32_t rh[4];
                uint32_t d = sw128(vL + (uint32_t)(ksv * 16 * 128 + dg * 32));
                ldsm4t(rh, vb + d);
                uint32_t vh0[2] = {rh[0], rh[1]}, vh1[2] = {rh[2], rh[3]};
                mma16816(o[dg*2],   ph[ksv], vh0);
                mma16816(o[dg*2+1], ph[ksv], vh1);
            }
        }
        __syncthreads();
    }

    // epilogue: single fp16 attn-out
    float inv0 = 1.f / l0, inv1 = 1.f / l1;
    int qi = q0 + warpM + (lane >> 2);
    size_t ro0 = ((size_t)(bh >> 4) * TT + qi) * CC + (size_t)(bh & 15) * DD;
    size_t ro1 = ro0 + (size_t)8 * CC;
    #pragma unroll
    for (int dt = 0; dt < 8; dt++) {
        int col = dt * 8 + (lane & 3) * 2;
        *(uint32_t*)(g_att + ro0 + col) = pack2h(o[dt][0] * inv0, o[dt][1] * inv0);
        *(uint32_t*)(g_att + ro1 + col) = pack2h(o[dt][2] * inv1, o[dt][3] * inv1);
    }
}

// ---------------------------------------------------------------------------
extern "C" void kernel_launch(void* const* d_in, const int* in_sizes, int n_in,
                              void* d_out, int out_size)
{
    const float* x      = (const float*)d_in[0];
    const float* w_attn = (const float*)d_in[1];
    const float* b_attn = (const float*)d_in[2];
    const float* w_proj = (const float*)d_in[3];
    const float* b_proj = (const float*)d_in[4];
    float* out = (float*)d_out;

    __half *xh, *xl, *wq, *wp, *att;
    cudaGetSymbolAddress((void**)&xh,  g_x_hi);
    cudaGetSymbolAddress((void**)&xl,  g_x_lo);
    cudaGetSymbolAddress((void**)&wq,  g_wq);
    cudaGetSymbolAddress((void**)&wp,  g_wp);
    cudaGetSymbolAddress((void**)&att, g_att);

    cudaFuncSetAttribute((const void*)gemm_mma<true, 2>,
                         cudaFuncAttributeMaxDynamicSharedMemorySize, GEMM_SMEM2);
    cudaFuncSetAttribute((const void*)gemm_mma<false, 1>,
                         cudaFuncAttributeMaxDynamicSharedMemorySize, GEMM_SMEM1);
    cudaFuncSetAttribute(attn_mma, cudaFuncAttributeMaxDynamicSharedMemorySize, ATT_SMEM);

    split_kernel<<<4096, 256>>>(x, xh, xl);
    tboth_kernel<<<dim3(128, 32), dim3(32, 32)>>>(w_attn, w_proj, wq, wp);

    gemm_mma<true, 2><<<dim3(24, 32), 128, GEMM_SMEM2>>>(xh, xl, wq, b_attn, nullptr, 3072);
    attn_mma<<<dim3(TT / 64, BB * HH), 128, ATT_SMEM>>>();
    gemm_mma<false, 1><<<dim3(8, 32), 128, GEMM_SMEM1>>>(att, nullptr, wp, b_proj, out, 1024);
}

// round 16
// speedup vs baseline: 1.0335x; 1.0183x over previous
#include <cuda_runtime.h>
#include <cuda_fp16.h>
#include <cstdint>

#define BB 2
#define TT 2048
#define CC 1024
#define HH 16
#define DD 64
#define BHTD (BB*HH*TT*DD)   // 4,194,304

// ---------------------------------------------------------------------------
// Scratch (__device__ globals; allocation-free rule)
// ---------------------------------------------------------------------------
__device__ __align__(16) __half g_x_hi[4096ll * 1024];
__device__ __align__(16) __half g_x_lo[4096ll * 1024];
__device__ __align__(16) __half g_wq[3072ll * 1024];        // w_attn^T [N,K] single fp16
__device__ __align__(16) __half g_wp[1024ll * 1024];        // w_proj^T [N,K] single fp16
__device__ __align__(16) __half g_att[4096ll * 1024];       // attn out [M,K] single fp16
// QKV outputs, [B*H, T, D]: q split hi/lo (pre-scaled by 0.125*log2e), k/v single
__device__ __align__(16) __half g_q_hi[BHTD];
__device__ __align__(16) __half g_q_lo[BHTD];
__device__ __align__(16) __half g_k[BHTD];
__device__ __align__(16) __half g_v[BHTD];

// ---------------------------------------------------------------------------
// Helpers
// ---------------------------------------------------------------------------
__device__ __forceinline__ uint32_t smem_u32(const void* p) {
    uint32_t a;
    asm("{ .reg .u64 t; cvta.to.shared.u64 t, %1; cvt.u32.u64 %0, t; }" : "=r"(a) : "l"(p));
    return a;
}
__device__ __forceinline__ void cp_async16(uint32_t dst, const void* src) {
    asm volatile("cp.async.cg.shared.global [%0], [%1], 16;" :: "r"(dst), "l"(src));
}
#define CP_COMMIT() asm volatile("cp.async.commit_group;" ::: "memory")
__device__ __forceinline__ uint32_t sw64(uint32_t off)  { return off ^ ((off >> 3) & 0x30); }
__device__ __forceinline__ uint32_t sw128(uint32_t off) { return off ^ ((off >> 3) & 0x70); }

__device__ __forceinline__ void ldsm4(uint32_t* r, uint32_t addr) {
    asm volatile("ldmatrix.sync.aligned.m8n8.x4.shared.b16 {%0,%1,%2,%3}, [%4];"
        : "=r"(r[0]), "=r"(r[1]), "=r"(r[2]), "=r"(r[3]) : "r"(addr));
}
__device__ __forceinline__ void ldsm4t(uint32_t* r, uint32_t addr) {
    asm volatile("ldmatrix.sync.aligned.m8n8.x4.trans.shared.b16 {%0,%1,%2,%3}, [%4];"
        : "=r"(r[0]), "=r"(r[1]), "=r"(r[2]), "=r"(r[3]) : "r"(addr));
}
// fp16 MMA with fp32 accumulate
__device__ __forceinline__ void mma16816(float* d, const uint32_t* a, const uint32_t* b) {
    asm volatile("mma.sync.aligned.m16n8k16.row.col.f32.f16.f16.f32 "
        "{%0,%1,%2,%3}, {%4,%5,%6,%7}, {%8,%9}, {%0,%1,%2,%3};"
        : "+f"(d[0]), "+f"(d[1]), "+f"(d[2]), "+f"(d[3])
        : "r"(a[0]), "r"(a[1]), "r"(a[2]), "r"(a[3]), "r"(b[0]), "r"(b[1]));
}
__device__ __forceinline__ void split2h(float x, float y, uint32_t& hi, uint32_t& lo) {
    __half hx = __float2half_rn(x), hy = __float2half_rn(y);
    __half lx = __float2half_rn(x - __half2float(hx));
    __half ly = __float2half_rn(y - __half2float(hy));
    __half2 h2 = __halves2half2(hx, hy);
    __half2 l2 = __halves2half2(lx, ly);
    hi = *reinterpret_cast<uint32_t*>(&h2);
    lo = *reinterpret_cast<uint32_t*>(&l2);
}
__device__ __forceinline__ uint32_t pack2h(float x, float y) {
    __half2 h = __floats2half2_rn(x, y);
    return *reinterpret_cast<uint32_t*>(&h);
}
// p = exp2(arg) computed in fp16x2 (half the MUFU ops, output pre-packed)
__device__ __forceinline__ uint32_t ex2_f16x2(float a, float b) {
    uint32_t arg = pack2h(a, b);
    uint32_t r;
    asm("ex2.approx.f16x2 %0, %1;" : "=r"(r) : "r"(arg));
    return r;
}

// ---------------------------------------------------------------------------
// Prepass kernels
// ---------------------------------------------------------------------------
__global__ void split_kernel(const float* __restrict__ X,
                             __half* __restrict__ hi, __half* __restrict__ lo)
{
    int i = blockIdx.x * blockDim.x + threadIdx.x;
    float4 v = ((const float4*)X)[i];
    uint32_t h0, l0, h1, l1;
    split2h(v.x, v.y, h0, l0);
    split2h(v.z, v.w, h1, l1);
    *(uint32_t*)(hi + (size_t)i * 4)     = h0;
    *(uint32_t*)(hi + (size_t)i * 4 + 2) = h1;
    *(uint32_t*)(lo + (size_t)i * 4)     = l0;
    *(uint32_t*)(lo + (size_t)i * 4 + 2) = l1;
}

// Fused transpose of both weight matrices: W [K,N] fp32 -> T [N,K] fp16.
__global__ void tboth_kernel(const float* __restrict__ Wq,
                             const float* __restrict__ Wp,
                             __half* __restrict__ Tq,
                             __half* __restrict__ Tp)
{
    __shared__ float ts[32][33];
    const float* W;
    __half* T;
    int Ncols, bx = blockIdx.x;
    if (bx < 96) { W = Wq; T = Tq; Ncols = 3072; }
    else         { W = Wp; T = Tp; Ncols = 1024; bx -= 96; }
    int n0 = bx * 32, k0 = blockIdx.y * 32;
    int tx = threadIdx.x, ty = threadIdx.y;
    ts[ty][tx] = W[(size_t)(k0 + ty) * Ncols + n0 + tx];
    __syncthreads();
    T[(size_t)(n0 + ty) * 1024 + k0 + tx] = __float2half_rn(ts[tx][ty]);
}

// ---------------------------------------------------------------------------
// fp16 GEMM via mma.sync, TERMS in {1,2} (R12 structure, unchanged).
// ---------------------------------------------------------------------------
#define ARR   8192                  // 128 rows x 64B
#define NSTG 3
#define NK 32

template<int TERMS>
__device__ __forceinline__ void load_stage(
    int tid, int kt, uint32_t sbase,
    const __half* Ahi, const __half* Alo, const __half* Bh,
    int m0, int n0)
{
    constexpr int STAGE = (TERMS + 1) * ARR;
    const uint32_t st = sbase + (uint32_t)((kt % NSTG) * STAGE);
    const int k0 = kt * 32;
    #pragma unroll
    for (int i = 0; i < 4; i++) {
        int idx = tid + i * 128;                 // 0..511 16B-chunks
        int r = idx >> 2, c = idx & 3;
        uint32_t d = sw64((uint32_t)idx * 16);
        size_t goA = (size_t)(m0 + r) * 1024 + k0 + c * 8;
        size_t goB = (size_t)(n0 + r) * 1024 + k0 + c * 8;
        cp_async16(st + d, Ahi + goA);
        if (TERMS == 2) cp_async16(st + ARR + d, Alo + goA);
        cp_async16(st + TERMS * ARR + d, Bh + goB);
    }
    CP_COMMIT();
}

template<bool QKV_EP, int TERMS>
__global__ void __launch_bounds__(128, 2) gemm_mma(
    const __half* __restrict__ Ahi, const __half* __restrict__ Alo,
    const __half* __restrict__ Bh2,
    const float* __restrict__ bias, float* __restrict__ Cout, int N)
{
    constexpr int STAGE = (TERMS + 1) * ARR;
    extern __shared__ __align__(128) char smem[];
    const uint32_t sb = smem_u32(smem);
    const int tid  = threadIdx.x;
    const int wid  = tid >> 5;
    const int lane = tid & 31;
    const int m0 = blockIdx.y * 128;
    const int n0 = blockIdx.x * 128;
    const int warpM = (wid >> 1) * 64;
    const int warpN = (wid & 1) * 64;

    float acc[4][8][4];
    #pragma unroll
    for (int i = 0; i < 4; i++)
        #pragma unroll
        for (int j = 0; j < 8; j++)
            #pragma unroll
            for (int e = 0; e < 4; e++) acc[i][j][e] = 0.f;

    const uint32_t aL = (uint32_t)((warpM + (lane & 15)) * 64 + (lane >> 4) * 16);
    const int brow = (lane & 7) + ((lane >> 4) << 3);
    const uint32_t bL = (uint32_t)((warpN + brow) * 64 + ((lane >> 3) & 1) * 16);

    load_stage<TERMS>(tid, 0, sb, Ahi, Alo, Bh2, m0, n0);
    load_stage<TERMS>(tid, 1, sb, Ahi, Alo, Bh2, m0, n0);

    for (int kt = 0; kt < NK; kt++) {
        if (kt + 1 < NK) asm volatile("cp.async.wait_group 1;" ::: "memory");
        else             asm volatile("cp.async.wait_group 0;" ::: "memory");
        __syncthreads();
        if (kt + 2 < NK)
            load_stage<TERMS>(tid, kt + 2, sb, Ahi, Alo, Bh2, m0, n0);

        const uint32_t st = sb + (uint32_t)((kt % NSTG) * STAGE);
        #pragma unroll
        for (int ks = 0; ks < 2; ks++) {
            uint32_t ah[4][4], al[4][4], bh[8][2];
            #pragma unroll
            for (int mt = 0; mt < 4; mt++) {
                uint32_t d = sw64(aL + (uint32_t)(mt * 1024 + ks * 32));
                ldsm4(ah[mt], st + d);
                if (TERMS == 2) ldsm4(al[mt], st + ARR + d);
            }
            #pragma unroll
            for (int np = 0; np < 4; np++) {
                uint32_t d = sw64(bL + (uint32_t)(np * 1024 + ks * 32));
                uint32_t r[4];
                ldsm4(r, st + TERMS * ARR + d);
                bh[np*2][0] = r[0]; bh[np*2][1] = r[1];
                bh[np*2+1][0] = r[2]; bh[np*2+1][1] = r[3];
            }
            #pragma unroll
            for (int mt = 0; mt < 4; mt++)
                #pragma unroll
                for (int nt = 0; nt < 8; nt++)
                    mma16816(acc[mt][nt], ah[mt], bh[nt]);
            if (TERMS == 2) {
                #pragma unroll
                for (int mt = 0; mt < 4; mt++)
                    #pragma unroll
                    for (int nt = 0; nt < 8; nt++)
                        mma16816(acc[mt][nt], al[mt], bh[nt]);
            }
        }
    }

    const int gid = lane >> 2;
    const int tig = lane & 3;
    const float QSCALE = 0.18033688011112042f;   // 0.125 * log2(e)
    #pragma unroll
    for (int mt = 0; mt < 4; mt++) {
        #pragma unroll
        for (int nt = 0; nt < 8; nt++) {
            int n = n0 + warpN + nt * 8 + tig * 2;
            float bx = bias[n], by = bias[n + 1];
            #pragma unroll
            for (int half = 0; half < 2; half++) {
                int m = m0 + warpM + mt * 16 + gid + half * 8;
                float vx = acc[mt][nt][half * 2 + 0] + bx;
                float vy = acc[mt][nt][half * 2 + 1] + by;
                if (QKV_EP) {
                    int which = n >> 10;
                    int hh = (n >> 6) & 15;
                    int dd = n & 63;
                    int bb = m >> 11;
                    int tt = m & 2047;
                    size_t off = (((size_t)bb * HH + hh) * TT + tt) * DD + dd;
                    if (which == 0) {
                        uint32_t hi, lo;
                        split2h(vx * QSCALE, vy * QSCALE, hi, lo);
                        *(uint32_t*)(g_q_hi + off) = hi;
                        *(uint32_t*)(g_q_lo + off) = lo;
                    } else {
                        __half* p = (which == 1) ? g_k : g_v;
                        *(uint32_t*)(p + off) = pack2h(vx, vy);
                    }
                } else {
                    float2 v; v.x = vx; v.y = vy;
                    *(float2*)(Cout + (size_t)m * N + n) = v;
                }
            }
        }
    }
}

#define GEMM_SMEM2 (NSTG * 3 * ARR)   // TERMS=2: 73728
#define GEMM_SMEM1 (NSTG * 2 * ARR)   // TERMS=1: 49152

// ---------------------------------------------------------------------------
// fp16 flash attention: Q split 2-term, K/V/P single. SW128, 128B rows,
// double-buffered. Smem 48KB -> 2 CTAs/SM. exp2 in fp16x2 (half MUFU ops,
// P pre-packed). Row-sum via MMA vs ones. Warp-voted rescale skip.
// ---------------------------------------------------------------------------
#define AT_TILE 8192                              // 64 rows x 128B
#define KV_BUF (2 * AT_TILE)                      // K,V = 16384
#define ATT_SMEM (2 * AT_TILE + 2 * KV_BUF)       // 49152

__global__ void __launch_bounds__(128, 2) attn_mma()
{
    extern __shared__ __align__(128) char smem[];
    const uint32_t sb = smem_u32(smem);
    const int tid  = threadIdx.x;
    const int wid  = tid >> 5;
    const int lane = tid & 31;
    const int bh = blockIdx.y;
    const int q0 = (int)(gridDim.x - 1 - blockIdx.x) * 64;   // big tiles first
    const int warpM = wid * 16;
    const size_t bhoff = (size_t)bh * TT * DD;

    const uint32_t kv0 = sb + 2 * AT_TILE;

    // --- load Q tile (hi+lo), SW128 ---
    {
        const __half* Qh = g_q_hi + bhoff + (size_t)q0 * DD;
        const __half* Ql = g_q_lo + bhoff + (size_t)q0 * DD;
        for (int i = tid; i < 512; i += 128) {
            uint32_t d = sw128((uint32_t)i * 16);
            size_t go = (size_t)i * 8;
            cp_async16(sb + d,           Qh + go);
            cp_async16(sb + AT_TILE + d, Ql + go);
        }
        CP_COMMIT();
    }

    const int njt = q0 / 64 + 1;

    // --- load K/V tile 0 ---
    {
        const __half* Kp = g_k + bhoff;
        const __half* Vp = g_v + bhoff;
        for (int i = tid; i < 512; i += 128) {
            uint32_t d = sw128((uint32_t)i * 16);
            size_t go = (size_t)i * 8;
            cp_async16(kv0 + d,           Kp + go);
            cp_async16(kv0 + AT_TILE + d, Vp + go);
        }
        CP_COMMIT();
    }

    asm volatile("cp.async.wait_group 1;" ::: "memory");
    __syncthreads();
    uint32_t qh[4][4], ql[4][4];
    const uint32_t aL = (uint32_t)((warpM + (lane & 15)) * 128 + (lane >> 4) * 16);
    #pragma unroll
    for (int ks = 0; ks < 4; ks++) {
        uint32_t d = sw128(aL + (uint32_t)(ks * 32));
        ldsm4(qh[ks], sb + d);
        ldsm4(ql[ks], sb + AT_TILE + d);
    }

    float o[8][4];
    #pragma unroll
    for (int i = 0; i < 8; i++)
        #pragma unroll
        for (int e = 0; e < 4; e++) o[i][e] = 0.f;
    float m0 = -1e30f, m1 = -1e30f, l0 = 0.f, l1 = 0.f;

    const uint32_t ones2[2] = {0x3C003C00u, 0x3C003C00u};   // fp16 1.0 x4

    const int brow = (lane & 7) + ((lane >> 4) << 3);
    const uint32_t bL = (uint32_t)(brow * 128 + ((lane >> 3) & 1) * 16);
    const int vrow = (lane & 7) + ((lane >> 3) & 1) * 8;
    const uint32_t vL = (uint32_t)(vrow * 128 + (lane >> 4) * 16);

    for (int jt = 0; jt < njt; jt++) {
        if (jt + 1 < njt) {
            uint32_t nb = kv0 + (uint32_t)(((jt + 1) & 1) * KV_BUF);
            size_t jo = (size_t)(jt + 1) * 64 * DD;
            const __half* Kp = g_k + bhoff + jo;
            const __half* Vp = g_v + bhoff + jo;
            for (int i = tid; i < 512; i += 128) {
                uint32_t d = sw128((uint32_t)i * 16);
                size_t go = (size_t)i * 8;
                cp_async16(nb + d,           Kp + go);
                cp_async16(nb + AT_TILE + d, Vp + go);
            }
            CP_COMMIT();
            asm volatile("cp.async.wait_group 1;" ::: "memory");
        } else {
            asm volatile("cp.async.wait_group 0;" ::: "memory");
        }
        __syncthreads();

        const uint32_t kb = kv0 + (uint32_t)((jt & 1) * KV_BUF);

        float s[8][4];
        #pragma unroll
        for (int i = 0; i < 8; i++)
            #pragma unroll
            for (int e = 0; e < 4; e++) s[i][e] = 0.f;

        // S = (Qh+Ql) Kh^T  (2 terms), scores in log2 units
        #pragma unroll
        for (int ks = 0; ks < 4; ks++) {
            #pragma unroll
            for (int np = 0; np < 4; np++) {
                uint32_t rh[4];
                uint32_t d = sw128(bL + (uint32_t)(np * 16 * 128 + ks * 32));
                ldsm4(rh, kb + d);
                uint32_t bh0[2] = {rh[0], rh[1]}, bh1[2] = {rh[2], rh[3]};
                mma16816(s[np*2],   qh[ks], bh0);
                mma16816(s[np*2+1], qh[ks], bh1);
                mma16816(s[np*2],   ql[ks], bh0);
                mma16816(s[np*2+1], ql[ks], bh1);
            }
        }

        if (jt == njt - 1) {
            int r0 = warpM + (lane >> 2);
            #pragma unroll
            for (int nt = 0; nt < 8; nt++) {
                int c0 = nt * 8 + (lane & 3) * 2;
                #pragma unroll
                for (int e = 0; e < 4; e++) {
                    int row = r0 + (e >> 1) * 8;
                    int col = c0 + (e & 1);
                    if (col > row) s[nt][e] = -1e30f;
                }
            }
        }

        float tm0 = -1e30f, tm1 = -1e30f;
        #pragma unroll
        for (int nt = 0; nt < 8; nt++) {
            tm0 = fmaxf(tm0, fmaxf(s[nt][0], s[nt][1]));
            tm1 = fmaxf(tm1, fmaxf(s[nt][2], s[nt][3]));
        }
        tm0 = fmaxf(tm0, __shfl_xor_sync(0xffffffff, tm0, 1));
        tm0 = fmaxf(tm0, __shfl_xor_sync(0xffffffff, tm0, 2));
        tm1 = fmaxf(tm1, __shfl_xor_sync(0xffffffff, tm1, 1));
        tm1 = fmaxf(tm1, __shfl_xor_sync(0xffffffff, tm1, 2));

        float nm0 = fmaxf(m0, tm0), nm1 = fmaxf(m1, tm1);
        float c0s = exp2f(m0 - nm0), c1s = exp2f(m1 - nm1);
        m0 = nm0; m1 = nm1;

        // P = exp2(s - m) directly in fp16x2 -> pre-packed A-fragments
        uint32_t ph[4][4];
        #pragma unroll
        for (int ksv = 0; ksv < 4; ksv++) {
            ph[ksv][0] = ex2_f16x2(s[2*ksv][0]   - nm0, s[2*ksv][1]   - nm0);
            ph[ksv][1] = ex2_f16x2(s[2*ksv][2]   - nm1, s[2*ksv][3]   - nm1);
            ph[ksv][2] = ex2_f16x2(s[2*ksv+1][0] - nm0, s[2*ksv+1][1] - nm0);
            ph[ksv][3] = ex2_f16x2(s[2*ksv+1][2] - nm1, s[2*ksv+1][3] - nm1);
        }

        // Row sums of P via MMA against ones-B: every lane gets its row's sum
        float lsum[4] = {0.f, 0.f, 0.f, 0.f};
        #pragma unroll
        for (int ksv = 0; ksv < 4; ksv++)
            mma16816(lsum, ph[ksv], ones2);

        // warp-voted rescale skip (exp2f(0) == 1.0f exactly)
        if (__all_sync(0xffffffff, (c0s == 1.f) & (c1s == 1.f))) {
            l0 += lsum[0];
            l1 += lsum[2];
        } else {
            l0 = l0 * c0s + lsum[0];
            l1 = l1 * c1s + lsum[2];
            #pragma unroll
            for (int dt = 0; dt < 8; dt++) {
                o[dt][0] *= c0s; o[dt][1] *= c0s;
                o[dt][2] *= c1s; o[dt][3] *= c1s;
            }
        }

        // O += P Vh  (1 term)
        const uint32_t vb = kb + AT_TILE;
        #pragma unroll
        for (int ksv = 0; ksv < 4; ksv++) {
            #pragma unroll
            for (int dg = 0; dg < 4; dg++) {
                uint32_t rh[4];
                uint32_t d = sw128(vL + (uint32_t)(ksv * 16 * 128 + dg * 32));
                ldsm4t(rh, vb + d);
                uint32_t vh0[2] = {rh[0], rh[1]}, vh1[2] = {rh[2], rh[3]};
                mma16816(o[dg*2],   ph[ksv], vh0);
                mma16816(o[dg*2+1], ph[ksv], vh1);
            }
        }
        __syncthreads();
    }

    // epilogue: single fp16 attn-out
    float inv0 = 1.f / l0, inv1 = 1.f / l1;
    int qi = q0 + warpM + (lane >> 2);
    size_t ro0 = ((size_t)(bh >> 4) * TT + qi) * CC + (size_t)(bh & 15) * DD;
    size_t ro1 = ro0 + (size_t)8 * CC;
    #pragma unroll
    for (int dt = 0; dt < 8; dt++) {
        int col = dt * 8 + (lane & 3) * 2;
        *(uint32_t*)(g_att + ro0 + col) = pack2h(o[dt][0] * inv0, o[dt][1] * inv0);
        *(uint32_t*)(g_att + ro1 + col) = pack2h(o[dt][2] * inv1, o[dt][3] * inv1);
    }
}

// ---------------------------------------------------------------------------
extern "C" void kernel_launch(void* const* d_in, const int* in_sizes, int n_in,
                              void* d_out, int out_size)
{
    const float* x      = (const float*)d_in[0];
    const float* w_attn = (const float*)d_in[1];
    const float* b_attn = (const float*)d_in[2];
    const float* w_proj = (const float*)d_in[3];
    const float* b_proj = (const float*)d_in[4];
    float* out = (float*)d_out;

    __half *xh, *xl, *wq, *wp, *att;
    cudaGetSymbolAddress((void**)&xh,  g_x_hi);
    cudaGetSymbolAddress((void**)&xl,  g_x_lo);
    cudaGetSymbolAddress((void**)&wq,  g_wq);
    cudaGetSymbolAddress((void**)&wp,  g_wp);
    cudaGetSymbolAddress((void**)&att, g_att);

    cudaFuncSetAttribute((const void*)gemm_mma<true, 2>,
                         cudaFuncAttributeMaxDynamicSharedMemorySize, GEMM_SMEM2);
    cudaFuncSetAttribute((const void*)gemm_mma<false, 1>,
                         cudaFuncAttributeMaxDynamicSharedMemorySize, GEMM_SMEM1);
    cudaFuncSetAttribute(attn_mma, cudaFuncAttributeMaxDynamicSharedMemorySize, ATT_SMEM);

    split_kernel<<<4096, 256>>>(x, xh, xl);
    tboth_kernel<<<dim3(128, 32), dim3(32, 32)>>>(w_attn, w_proj, wq, wp);

    gemm_mma<true, 2><<<dim3(24, 32), 128, GEMM_SMEM2>>>(xh, xl, wq, b_attn, nullptr, 3072);
    attn_mma<<<dim3(TT / 64, BB * HH), 128, ATT_SMEM>>>();
    gemm_mma<false, 1><<<dim3(8, 32), 128, GEMM_SMEM1>>>(att, nullptr, wp, b_proj, out, 1024);
}

// round 17
// speedup vs baseline: 1.3334x; 1.2902x over previous
#include <cuda_runtime.h>
#include <cuda_fp16.h>
#include <cstdint>

#define BB 2
#define TT 2048
#define CC 1024
#define HH 16
#define DD 64
#define BHTD (BB*HH*TT*DD)   // 4,194,304

// ---------------------------------------------------------------------------
// Scratch (__device__ globals; allocation-free rule)
// ---------------------------------------------------------------------------
__device__ __align__(16) __half g_x[4096ll * 1024];         // x single fp16
__device__ __align__(16) __half g_wq[3072ll * 1024];        // w_attn^T [N,K] single fp16
__device__ __align__(16) __half g_wp[1024ll * 1024];        // w_proj^T [N,K] single fp16
__device__ __align__(16) __half g_att[4096ll * 1024];       // attn out [M,K] single fp16
// QKV outputs, [B*H, T, D]: q split hi/lo (pre-scaled by 0.125*log2e), k/v single
__device__ __align__(16) __half g_q_hi[BHTD];
__device__ __align__(16) __half g_q_lo[BHTD];
__device__ __align__(16) __half g_k[BHTD];
__device__ __align__(16) __half g_v[BHTD];

// ---------------------------------------------------------------------------
// Helpers
// ---------------------------------------------------------------------------
__device__ __forceinline__ uint32_t smem_u32(const void* p) {
    uint32_t a;
    asm("{ .reg .u64 t; cvta.to.shared.u64 t, %1; cvt.u32.u64 %0, t; }" : "=r"(a) : "l"(p));
    return a;
}
__device__ __forceinline__ void cp_async16(uint32_t dst, const void* src) {
    asm volatile("cp.async.cg.shared.global [%0], [%1], 16;" :: "r"(dst), "l"(src));
}
#define CP_COMMIT() asm volatile("cp.async.commit_group;" ::: "memory")
__device__ __forceinline__ uint32_t sw64(uint32_t off)  { return off ^ ((off >> 3) & 0x30); }
__device__ __forceinline__ uint32_t sw128(uint32_t off) { return off ^ ((off >> 3) & 0x70); }

__device__ __forceinline__ void ldsm4(uint32_t* r, uint32_t addr) {
    asm volatile("ldmatrix.sync.aligned.m8n8.x4.shared.b16 {%0,%1,%2,%3}, [%4];"
        : "=r"(r[0]), "=r"(r[1]), "=r"(r[2]), "=r"(r[3]) : "r"(addr));
}
__device__ __forceinline__ void ldsm4t(uint32_t* r, uint32_t addr) {
    asm volatile("ldmatrix.sync.aligned.m8n8.x4.trans.shared.b16 {%0,%1,%2,%3}, [%4];"
        : "=r"(r[0]), "=r"(r[1]), "=r"(r[2]), "=r"(r[3]) : "r"(addr));
}
// fp16 MMA with fp32 accumulate
__device__ __forceinline__ void mma16816(float* d, const uint32_t* a, const uint32_t* b) {
    asm volatile("mma.sync.aligned.m16n8k16.row.col.f32.f16.f16.f32 "
        "{%0,%1,%2,%3}, {%4,%5,%6,%7}, {%8,%9}, {%0,%1,%2,%3};"
        : "+f"(d[0]), "+f"(d[1]), "+f"(d[2]), "+f"(d[3])
        : "r"(a[0]), "r"(a[1]), "r"(a[2]), "r"(a[3]), "r"(b[0]), "r"(b[1]));
}
__device__ __forceinline__ void split2h(float x, float y, uint32_t& hi, uint32_t& lo) {
    __half hx = __float2half_rn(x), hy = __float2half_rn(y);
    __half lx = __float2half_rn(x - __half2float(hx));
    __half ly = __float2half_rn(y - __half2float(hy));
    __half2 h2 = __halves2half2(hx, hy);
    __half2 l2 = __halves2half2(lx, ly);
    hi = *reinterpret_cast<uint32_t*>(&h2);
    lo = *reinterpret_cast<uint32_t*>(&l2);
}
__device__ __forceinline__ uint32_t pack2h(float x, float y) {
    __half2 h = __floats2half2_rn(x, y);
    return *reinterpret_cast<uint32_t*>(&h);
}
// p = exp2(arg) computed in fp16x2 (half the MUFU ops, output pre-packed)
__device__ __forceinline__ uint32_t ex2_f16x2(float a, float b) {
    uint32_t arg = pack2h(a, b);
    uint32_t r;
    asm("ex2.approx.f16x2 %0, %1;" : "=r"(r) : "r"(arg));
    return r;
}

// ---------------------------------------------------------------------------
// Prepass kernels
// ---------------------------------------------------------------------------
__global__ void cvt_kernel(const float* __restrict__ X, __half* __restrict__ H)
{
    int i = blockIdx.x * blockDim.x + threadIdx.x;
    float4 v = ((const float4*)X)[i];
    *(uint32_t*)(H + (size_t)i * 4)     = pack2h(v.x, v.y);
    *(uint32_t*)(H + (size_t)i * 4 + 2) = pack2h(v.z, v.w);
}

// Fused transpose of both weight matrices: W [K,N] fp32 -> T [N,K] fp16.
__global__ void tboth_kernel(const float* __restrict__ Wq,
                             const float* __restrict__ Wp,
                             __half* __restrict__ Tq,
                             __half* __restrict__ Tp)
{
    __shared__ float ts[32][33];
    const float* W;
    __half* T;
    int Ncols, bx = blockIdx.x;
    if (bx < 96) { W = Wq; T = Tq; Ncols = 3072; }
    else         { W = Wp; T = Tp; Ncols = 1024; bx -= 96; }
    int n0 = bx * 32, k0 = blockIdx.y * 32;
    int tx = threadIdx.x, ty = threadIdx.y;
    ts[ty][tx] = W[(size_t)(k0 + ty) * Ncols + n0 + tx];
    __syncthreads();
    T[(size_t)(n0 + ty) * 1024 + k0 + tx] = __float2half_rn(ts[tx][ty]);
}

// ---------------------------------------------------------------------------
// fp16 GEMM via mma.sync, TERMS in {1,2} (R12 structure).
// ---------------------------------------------------------------------------
#define ARR   8192                  // 128 rows x 64B
#define NSTG 3
#define NK 32

template<int TERMS>
__device__ __forceinline__ void load_stage(
    int tid, int kt, uint32_t sbase,
    const __half* Ahi, const __half* Alo, const __half* Bh,
    int m0, int n0)
{
    constexpr int STAGE = (TERMS + 1) * ARR;
    const uint32_t st = sbase + (uint32_t)((kt % NSTG) * STAGE);
    const int k0 = kt * 32;
    #pragma unroll
    for (int i = 0; i < 4; i++) {
        int idx = tid + i * 128;                 // 0..511 16B-chunks
        int r = idx >> 2, c = idx & 3;
        uint32_t d = sw64((uint32_t)idx * 16);
        size_t goA = (size_t)(m0 + r) * 1024 + k0 + c * 8;
        size_t goB = (size_t)(n0 + r) * 1024 + k0 + c * 8;
        cp_async16(st + d, Ahi + goA);
        if (TERMS == 2) cp_async16(st + ARR + d, Alo + goA);
        cp_async16(st + TERMS * ARR + d, Bh + goB);
    }
    CP_COMMIT();
}

template<bool QKV_EP, int TERMS>
__global__ void __launch_bounds__(128, 2) gemm_mma(
    const __half* __restrict__ Ahi, const __half* __restrict__ Alo,
    const __half* __restrict__ Bh2,
    const float* __restrict__ bias, float* __restrict__ Cout, int N)
{
    constexpr int STAGE = (TERMS + 1) * ARR;
    extern __shared__ __align__(128) char smem[];
    const uint32_t sb = smem_u32(smem);
    const int tid  = threadIdx.x;
    const int wid  = tid >> 5;
    const int lane = tid & 31;
    const int m0 = blockIdx.y * 128;
    const int n0 = blockIdx.x * 128;
    const int warpM = (wid >> 1) * 64;
    const int warpN = (wid & 1) * 64;

    float acc[4][8][4];
    #pragma unroll
    for (int i = 0; i < 4; i++)
        #pragma unroll
        for (int j = 0; j < 8; j++)
            #pragma unroll
            for (int e = 0; e < 4; e++) acc[i][j][e] = 0.f;

    const uint32_t aL = (uint32_t)((warpM + (lane & 15)) * 64 + (lane >> 4) * 16);
    const int brow = (lane & 7) + ((lane >> 4) << 3);
    const uint32_t bL = (uint32_t)((warpN + brow) * 64 + ((lane >> 3) & 1) * 16);

    load_stage<TERMS>(tid, 0, sb, Ahi, Alo, Bh2, m0, n0);
    load_stage<TERMS>(tid, 1, sb, Ahi, Alo, Bh2, m0, n0);

    for (int kt = 0; kt < NK; kt++) {
        if (kt + 1 < NK) asm volatile("cp.async.wait_group 1;" ::: "memory");
        else             asm volatile("cp.async.wait_group 0;" ::: "memory");
        __syncthreads();
        if (kt + 2 < NK)
            load_stage<TERMS>(tid, kt + 2, sb, Ahi, Alo, Bh2, m0, n0);

        const uint32_t st = sb + (uint32_t)((kt % NSTG) * STAGE);
        #pragma unroll
        for (int ks = 0; ks < 2; ks++) {
            uint32_t ah[4][4], al[4][4], bh[8][2];
            #pragma unroll
            for (int mt = 0; mt < 4; mt++) {
                uint32_t d = sw64(aL + (uint32_t)(mt * 1024 + ks * 32));
                ldsm4(ah[mt], st + d);
                if (TERMS == 2) ldsm4(al[mt], st + ARR + d);
            }
            #pragma unroll
            for (int np = 0; np < 4; np++) {
                uint32_t d = sw64(bL + (uint32_t)(np * 1024 + ks * 32));
                uint32_t r[4];
                ldsm4(r, st + TERMS * ARR + d);
                bh[np*2][0] = r[0]; bh[np*2][1] = r[1];
                bh[np*2+1][0] = r[2]; bh[np*2+1][1] = r[3];
            }
            #pragma unroll
            for (int mt = 0; mt < 4; mt++)
                #pragma unroll
                for (int nt = 0; nt < 8; nt++)
                    mma16816(acc[mt][nt], ah[mt], bh[nt]);
            if (TERMS == 2) {
                #pragma unroll
                for (int mt = 0; mt < 4; mt++)
                    #pragma unroll
                    for (int nt = 0; nt < 8; nt++)
                        mma16816(acc[mt][nt], al[mt], bh[nt]);
            }
        }
    }

    const int gid = lane >> 2;
    const int tig = lane & 3;
    const float QSCALE = 0.18033688011112042f;   // 0.125 * log2(e)
    #pragma unroll
    for (int mt = 0; mt < 4; mt++) {
        #pragma unroll
        for (int nt = 0; nt < 8; nt++) {
            int n = n0 + warpN + nt * 8 + tig * 2;
            float bx = bias[n], by = bias[n + 1];
            #pragma unroll
            for (int half = 0; half < 2; half++) {
                int m = m0 + warpM + mt * 16 + gid + half * 8;
                float vx = acc[mt][nt][half * 2 + 0] + bx;
                float vy = acc[mt][nt][half * 2 + 1] + by;
                if (QKV_EP) {
                    int which = n >> 10;
                    int hh = (n >> 6) & 15;
                    int dd = n & 63;
                    int bb = m >> 11;
                    int tt = m & 2047;
                    size_t off = (((size_t)bb * HH + hh) * TT + tt) * DD + dd;
                    if (which == 0) {
                        uint32_t hi, lo;
                        split2h(vx * QSCALE, vy * QSCALE, hi, lo);
                        *(uint32_t*)(g_q_hi + off) = hi;
                        *(uint32_t*)(g_q_lo + off) = lo;
                    } else {
                        __half* p = (which == 1) ? g_k : g_v;
                        *(uint32_t*)(p + off) = pack2h(vx, vy);
                    }
                } else {
                    float2 v; v.x = vx; v.y = vy;
                    *(float2*)(Cout + (size_t)m * N + n) = v;
                }
            }
        }
    }
}

#define GEMM_SMEM2 (NSTG * 3 * ARR)   // TERMS=2: 73728
#define GEMM_SMEM1 (NSTG * 2 * ARR)   // TERMS=1: 49152

// ---------------------------------------------------------------------------
// fp16 flash attention (R16 config, unchanged).
// ---------------------------------------------------------------------------
#define AT_TILE 8192                              // 64 rows x 128B
#define KV_BUF (2 * AT_TILE)                      // K,V = 16384
#define ATT_SMEM (2 * AT_TILE + 2 * KV_BUF)       // 49152

__global__ void __launch_bounds__(128, 2) attn_mma()
{
    extern __shared__ __align__(128) char smem[];
    const uint32_t sb = smem_u32(smem);
    const int tid  = threadIdx.x;
    const int wid  = tid >> 5;
    const int lane = tid & 31;
    const int bh = blockIdx.y;
    const int q0 = (int)(gridDim.x - 1 - blockIdx.x) * 64;   // big tiles first
    const int warpM = wid * 16;
    const size_t bhoff = (size_t)bh * TT * DD;

    const uint32_t kv0 = sb + 2 * AT_TILE;

    // --- load Q tile (hi+lo), SW128 ---
    {
        const __half* Qh = g_q_hi + bhoff + (size_t)q0 * DD;
        const __half* Ql = g_q_lo + bhoff + (size_t)q0 * DD;
        for (int i = tid; i < 512; i += 128) {
            uint32_t d = sw128((uint32_t)i * 16);
            size_t go = (size_t)i * 8;
            cp_async16(sb + d,           Qh + go);
            cp_async16(sb + AT_TILE + d, Ql + go);
        }
        CP_COMMIT();
    }

    const int njt = q0 / 64 + 1;

    // --- load K/V tile 0 ---
    {
        const __half* Kp = g_k + bhoff;
        const __half* Vp = g_v + bhoff;
        for (int i = tid; i < 512; i += 128) {
            uint32_t d = sw128((uint32_t)i * 16);
            size_t go = (size_t)i * 8;
            cp_async16(kv0 + d,           Kp + go);
            cp_async16(kv0 + AT_TILE + d, Vp + go);
        }
        CP_COMMIT();
    }

    asm volatile("cp.async.wait_group 1;" ::: "memory");
    __syncthreads();
    uint32_t qh[4][4], ql[4][4];
    const uint32_t aL = (uint32_t)((warpM + (lane & 15)) * 128 + (lane >> 4) * 16);
    #pragma unroll
    for (int ks = 0; ks < 4; ks++) {
        uint32_t d = sw128(aL + (uint32_t)(ks * 32));
        ldsm4(qh[ks], sb + d);
        ldsm4(ql[ks], sb + AT_TILE + d);
    }

    float o[8][4];
    #pragma unroll
    for (int i = 0; i < 8; i++)
        #pragma unroll
        for (int e = 0; e < 4; e++) o[i][e] = 0.f;
    float m0 = -1e30f, m1 = -1e30f, l0 = 0.f, l1 = 0.f;

    const uint32_t ones2[2] = {0x3C003C00u, 0x3C003C00u};   // fp16 1.0 x4

    const int brow = (lane & 7) + ((lane >> 4) << 3);
    const uint32_t bL = (uint32_t)(brow * 128 + ((lane >> 3) & 1) * 16);
    const int vrow = (lane & 7) + ((lane >> 3) & 1) * 8;
    const uint32_t vL = (uint32_t)(vrow * 128 + (lane >> 4) * 16);

    for (int jt = 0; jt < njt; jt++) {
        if (jt + 1 < njt) {
            uint32_t nb = kv0 + (uint32_t)(((jt + 1) & 1) * KV_BUF);
            size_t jo = (size_t)(jt + 1) * 64 * DD;
            const __half* Kp = g_k + bhoff + jo;
            const __half* Vp = g_v + bhoff + jo;
            for (int i = tid; i < 512; i += 128) {
                uint32_t d = sw128((uint32_t)i * 16);
                size_t go = (size_t)i * 8;
                cp_async16(nb + d,           Kp + go);
                cp_async16(nb + AT_TILE + d, Vp + go);
            }
            CP_COMMIT();
            asm volatile("cp.async.wait_group 1;" ::: "memory");
        } else {
            asm volatile("cp.async.wait_group 0;" ::: "memory");
        }
        __syncthreads();

        const uint32_t kb = kv0 + (uint32_t)((jt & 1) * KV_BUF);

        float s[8][4];
        #pragma unroll
        for (int i = 0; i < 8; i++)
            #pragma unroll
            for (int e = 0; e < 4; e++) s[i][e] = 0.f;

        // S = (Qh+Ql) Kh^T  (2 terms), scores in log2 units
        #pragma unroll
        for (int ks = 0; ks < 4; ks++) {
            #pragma unroll
            for (int np = 0; np < 4; np++) {
                uint32_t rh[4];
                uint32_t d = sw128(bL + (uint32_t)(np * 16 * 128 + ks * 32));
                ldsm4(rh, kb + d);
                uint32_t bh0[2] = {rh[0], rh[1]}, bh1[2] = {rh[2], rh[3]};
                mma16816(s[np*2],   qh[ks], bh0);
                mma16816(s[np*2+1], qh[ks], bh1);
                mma16816(s[np*2],   ql[ks], bh0);
                mma16816(s[np*2+1], ql[ks], bh1);
            }
        }

        if (jt == njt - 1) {
            int r0 = warpM + (lane >> 2);
            #pragma unroll
            for (int nt = 0; nt < 8; nt++) {
                int c0 = nt * 8 + (lane & 3) * 2;
                #pragma unroll
                for (int e = 0; e < 4; e++) {
                    int row = r0 + (e >> 1) * 8;
                    int col = c0 + (e & 1);
                    if (col > row) s[nt][e] = -1e30f;
                }
            }
        }

        float tm0 = -1e30f, tm1 = -1e30f;
        #pragma unroll
        for (int nt = 0; nt < 8; nt++) {
            tm0 = fmaxf(tm0, fmaxf(s[nt][0], s[nt][1]));
            tm1 = fmaxf(tm1, fmaxf(s[nt][2], s[nt][3]));
        }
        tm0 = fmaxf(tm0, __shfl_xor_sync(0xffffffff, tm0, 1));
        tm0 = fmaxf(tm0, __shfl_xor_sync(0xffffffff, tm0, 2));
        tm1 = fmaxf(tm1, __shfl_xor_sync(0xffffffff, tm1, 1));
        tm1 = fmaxf(tm1, __shfl_xor_sync(0xffffffff, tm1, 2));

        float nm0 = fmaxf(m0, tm0), nm1 = fmaxf(m1, tm1);
        float c0s = exp2f(m0 - nm0), c1s = exp2f(m1 - nm1);
        m0 = nm0; m1 = nm1;

        // P = exp2(s - m) directly in fp16x2 -> pre-packed A-fragments
        uint32_t ph[4][4];
        #pragma unroll
        for (int ksv = 0; ksv < 4; ksv++) {
            ph[ksv][0] = ex2_f16x2(s[2*ksv][0]   - nm0, s[2*ksv][1]   - nm0);
            ph[ksv][1] = ex2_f16x2(s[2*ksv][2]   - nm1, s[2*ksv][3]   - nm1);
            ph[ksv][2] = ex2_f16x2(s[2*ksv+1][0] - nm0, s[2*ksv+1][1] - nm0);
            ph[ksv][3] = ex2_f16x2(s[2*ksv+1][2] - nm1, s[2*ksv+1][3] - nm1);
        }

        // Row sums of P via MMA against ones-B
        float lsum[4] = {0.f, 0.f, 0.f, 0.f};
        #pragma unroll
        for (int ksv = 0; ksv < 4; ksv++)
            mma16816(lsum, ph[ksv], ones2);

        // warp-voted rescale skip (exp2f(0) == 1.0f exactly)
        if (__all_sync(0xffffffff, (c0s == 1.f) & (c1s == 1.f))) {
            l0 += lsum[0];
            l1 += lsum[2];
        } else {
            l0 = l0 * c0s + lsum[0];
            l1 = l1 * c1s + lsum[2];
            #pragma unroll
            for (int dt = 0; dt < 8; dt++) {
                o[dt][0] *= c0s; o[dt][1] *= c0s;
                o[dt][2] *= c1s; o[dt][3] *= c1s;
            }
        }

        // O += P Vh  (1 term)
        const uint32_t vb = kb + AT_TILE;
        #pragma unroll
        for (int ksv = 0; ksv < 4; ksv++) {
            #pragma unroll
            for (int dg = 0; dg < 4; dg++) {
                uint32_t rh[4];
                uint32_t d = sw128(vL + (uint32_t)(ksv * 16 * 128 + dg * 32));
                ldsm4t(rh, vb + d);
                uint32_t vh0[2] = {rh[0], rh[1]}, vh1[2] = {rh[2], rh[3]};
                mma16816(o[dg*2],   ph[ksv], vh0);
                mma16816(o[dg*2+1], ph[ksv], vh1);
            }
        }
        __syncthreads();
    }

    // epilogue: single fp16 attn-out
    float inv0 = 1.f / l0, inv1 = 1.f / l1;
    int qi = q0 + warpM + (lane >> 2);
    size_t ro0 = ((size_t)(bh >> 4) * TT + qi) * CC + (size_t)(bh & 15) * DD;
    size_t ro1 = ro0 + (size_t)8 * CC;
    #pragma unroll
    for (int dt = 0; dt < 8; dt++) {
        int col = dt * 8 + (lane & 3) * 2;
        *(uint32_t*)(g_att + ro0 + col) = pack2h(o[dt][0] * inv0, o[dt][1] * inv0);
        *(uint32_t*)(g_att + ro1 + col) = pack2h(o[dt][2] * inv1, o[dt][3] * inv1);
    }
}

// ---------------------------------------------------------------------------
extern "C" void kernel_launch(void* const* d_in, const int* in_sizes, int n_in,
                              void* d_out, int out_size)
{
    const float* x      = (const float*)d_in[0];
    const float* w_attn = (const float*)d_in[1];
    const float* b_attn = (const float*)d_in[2];
    const float* w_proj = (const float*)d_in[3];
    const float* b_proj = (const float*)d_in[4];
    float* out = (float*)d_out;

    __half *xh, *wq, *wp, *att;
    cudaGetSymbolAddress((void**)&xh,  g_x);
    cudaGetSymbolAddress((void**)&wq,  g_wq);
    cudaGetSymbolAddress((void**)&wp,  g_wp);
    cudaGetSymbolAddress((void**)&att, g_att);

    cudaFuncSetAttribute((const void*)gemm_mma<true, 1>,
                         cudaFuncAttributeMaxDynamicSharedMemorySize, GEMM_SMEM1);
    cudaFuncSetAttribute((const void*)gemm_mma<false, 1>,
                         cudaFuncAttributeMaxDynamicSharedMemorySize, GEMM_SMEM1);
    cudaFuncSetAttribute(attn_mma, cudaFuncAttributeMaxDynamicSharedMemorySize, ATT_SMEM);

    cvt_kernel<<<4096, 256>>>(x, xh);
    tboth_kernel<<<dim3(128, 32), dim3(32, 32)>>>(w_attn, w_proj, wq, wp);

    gemm_mma<true, 1><<<dim3(24, 32), 128, GEMM_SMEM1>>>(xh, nullptr, wq, b_attn, nullptr, 3072);
    attn_mma<<<dim3(TT / 64, BB * HH), 128, ATT_SMEM>>>();
    gemm_mma<false, 1><<<dim3(8, 32), 128, GEMM_SMEM1>>>(att, nullptr, wp, b_proj, out, 1024);
}